// round 14
// baseline (speedup 1.0000x reference)
#include <cuda_runtime.h>
#include <cuda_fp16.h>
#include <cstdint>

// out[b,o] = x @ w_eff^T,  w_eff[o,i] = (sum_p coef[o,i,p]) * weights[o,i]
// Single fp16 GEMM on HMMA (m16n8k16, fp32 accum): C = fp16(x) @ fp16(w_eff)^T
// rel_err 2.93e-4 (calibrated), threshold 1e-3.
// R14: x->fp16 conversion fused INTO the GEMM (cp.async fp32 staging ->
// in-CTA convert -> proven HMMA mainloop). Only w_eff prep remains external.

#define BATCH 8192
#define IN    1024
#define OUT   1024
#define PDIM  8

__device__ __half g_bhi[OUT * IN];   // [O,I] row-major == B^T [N,K]

// ============================ w_eff prep kernel ============================
#define WB ((OUT * IN / 2) / 256)     // 2048 blocks, 2 outputs/thread

__global__ __launch_bounds__(256) void weff_kernel(
    const float* __restrict__ coef, const float* __restrict__ w)
{
    int i2 = blockIdx.x * 256 + threadIdx.x;           // over O*I/2
    const float4* c4 = reinterpret_cast<const float4*>(coef) + (size_t)i2 * 4;
    float4 a0 = c4[0], a1 = c4[1], a2 = c4[2], a3 = c4[3];
    float2 wv = reinterpret_cast<const float2*>(w)[i2];
    float s0 = (((a0.x + a0.y) + (a0.z + a0.w)) + ((a1.x + a1.y) + (a1.z + a1.w))) * wv.x;
    float s1 = (((a2.x + a2.y) + (a2.z + a2.w)) + ((a3.x + a3.y) + (a3.z + a3.w))) * wv.y;
    union { __half h[2]; uint32_t u; } o;
    o.h[0] = __float2half_rn(s0);
    o.h[1] = __float2half_rn(s1);
    reinterpret_cast<uint32_t*>(g_bhi)[i2] = o.u;
}

// ============================ GEMM ============================
// Block 256x128x64, 256 threads (8 warps, 4x2), warp tile 64x64.
// A path: cp.async fp32 x tile -> smem staging (2 bufs) -> convert to fp16
//         smem tile (1 buf, ROWB=72 layout) -> ldmatrix (unchanged).
// B path: cp.async fp16 (3 stages, unchanged).
// 1 cp.async commit group per k-iter; cp_wait<1>; 2 syncthreads per iter.
#define BM 256
#define BN 128
#define BK 64
#define KITERS 16          // 1024/64
#define HALVES 4           // k16 halves per BK=64

#define ROWB 72            // halfs per smem row (144B stride, conflict-free)
// byte offsets within dynamic smem
#define SA32_BYTES (BM * BK * 4)            // 65536 per fp32 staging buffer
#define OFF_SA0   0
#define OFF_SA1   (SA32_BYTES)              // 65536
#define OFF_A16   (2 * SA32_BYTES)          // 131072
#define A16_BYTES (BM * ROWB * 2)           // 36864
#define OFF_B0    (OFF_A16 + A16_BYTES)     // 167936
#define B_BYTES   (BN * ROWB * 2)           // 18432
#define SMEM_BYTES (OFF_B0 + 3 * B_BYTES)   // 223232

__device__ __forceinline__ uint32_t smem_u32(const void* p) {
    uint32_t a;
    asm("{ .reg .u64 t; cvta.to.shared.u64 t, %1; cvt.u32.u64 %0, t; }" : "=r"(a) : "l"(p));
    return a;
}
__device__ __forceinline__ void cp16(uint32_t dst, const void* src) {
    asm volatile("cp.async.cg.shared.global [%0], [%1], 16;" :: "r"(dst), "l"(src));
}
__device__ __forceinline__ void cp_commit() {
    asm volatile("cp.async.commit_group;");
}
template <int N>
__device__ __forceinline__ void cp_wait() {
    asm volatile("cp.async.wait_group %0;" :: "n"(N));
}
__device__ __forceinline__ void ldmx4(uint32_t* r, uint32_t addr) {
    asm volatile("ldmatrix.sync.aligned.m8n8.x4.shared.b16 {%0,%1,%2,%3}, [%4];"
                 : "=r"(r[0]), "=r"(r[1]), "=r"(r[2]), "=r"(r[3]) : "r"(addr));
}
__device__ __forceinline__ void hmma(float* c, const uint32_t* a, const uint32_t* b) {
    asm volatile(
        "mma.sync.aligned.m16n8k16.row.col.f32.f16.f16.f32 "
        "{%0,%1,%2,%3}, {%4,%5,%6,%7}, {%8,%9}, {%0,%1,%2,%3};"
        : "+f"(c[0]), "+f"(c[1]), "+f"(c[2]), "+f"(c[3])
        : "r"(a[0]), "r"(a[1]), "r"(a[2]), "r"(a[3]), "r"(b[0]), "r"(b[1]));
}

__global__ __launch_bounds__(256, 1) void gemm_hmma(
    const float* __restrict__ X, float* __restrict__ C)
{
    extern __shared__ char smem[];
    const uint32_t sbase = smem_u32(smem);

    const int tid = threadIdx.x;
    const int wid = tid >> 5;
    const int lid = tid & 31;
    const int warp_m = (wid & 3) * 64;     // 4 warps along M
    const int warp_n = (wid >> 2) * 64;    // 2 warps along N

    const int bm = blockIdx.y * BM;
    const int bn = blockIdx.x * BN;

    const uint32_t sa[2]  = {sbase + OFF_SA0, sbase + OFF_SA1};
    const uint32_t a16    = sbase + OFF_A16;
    const uint32_t sb[3]  = {sbase + OFF_B0, sbase + OFF_B0 + B_BYTES,
                             sbase + OFF_B0 + 2 * B_BYTES};

    // A fp32 staging cp.async mapping: tile = 256 rows x 256B = 4096 chunks,
    // 16/thread: rows (tid>>4)+16q, fixed seg tid&15 (consecutive tids -> consecutive 16B).
    const int a_srow = tid >> 4;           // 0..15
    const int a_sseg = tid & 15;           // 16B chunk in row
    // B cp.async mapping (unchanged): 128 rows x 128B, 4/thread
    const int ld_row = tid >> 3;           // 0..31
    const int ld_seg = (tid & 7) * 8;      // half offset in row

    float acc[4][8][4];
#pragma unroll
    for (int i = 0; i < 4; i++)
#pragma unroll
        for (int j = 0; j < 8; j++)
#pragma unroll
            for (int q = 0; q < 4; q++) acc[i][j][q] = 0.f;

    // ldmatrix lane addressing (byte offsets within fp16 A tile / B stage)
    const int a_lrow = warp_m + (lid & 15);
    const int a_lcol = (lid >> 4) * 16;
    const int b_lrow = warp_n + ((lid >> 4) << 3) + (lid & 7);
    const int b_lcol = ((lid >> 3) & 1) * 16;

    auto issue_tile = [&](int kt) {
        const int ko = kt * BK;
        const uint32_t ab = sa[kt & 1];
        const uint32_t bb = sb[kt % 3];
#pragma unroll
        for (int q = 0; q < 16; q++) {
            const int row = a_srow + q * 16;
            cp16(ab + row * 256 + a_sseg * 16,
                 &X[(size_t)(bm + row) * IN + ko + a_sseg * 4]);
        }
#pragma unroll
        for (int q = 0; q < 4; q++) {
            const int row = ld_row + q * 32;
            cp16(bb + (row * ROWB + ld_seg) * 2,
                 &g_bhi[(size_t)(bn + row) * IN + ko + ld_seg]);
        }
        cp_commit();
    };

    issue_tile(0);
    issue_tile(1);

    for (int kt = 0; kt < KITERS; kt++) {
        cp_wait<1>();          // tile kt arrived (kt+1 may be in flight)
        __syncthreads();       // cross-thread visibility of staging + B

        // ---- convert fp32 staging[kt&1] -> fp16 A tile (row tid) ----
        {
            const uint32_t src = sa[kt & 1] + tid * 256;   // my row, fp32
            const uint32_t dst = a16 + tid * 144;          // my row, fp16 (ROWB=72)
#pragma unroll
            for (int i = 0; i < 16; i++) {
                const int j = (i + tid) & 15;              // bank rotation
                float4 v;
                asm volatile("ld.shared.v4.f32 {%0,%1,%2,%3}, [%4];"
                             : "=f"(v.x), "=f"(v.y), "=f"(v.z), "=f"(v.w)
                             : "r"(src + j * 16));
                __half2 h0 = __floats2half2_rn(v.x, v.y);
                __half2 h1 = __floats2half2_rn(v.z, v.w);
                uint32_t u0 = *reinterpret_cast<uint32_t*>(&h0);
                uint32_t u1 = *reinterpret_cast<uint32_t*>(&h1);
                asm volatile("st.shared.v2.u32 [%0], {%1,%2};"
                             :: "r"(dst + j * 8), "r"(u0), "r"(u1));
            }
        }
        __syncthreads();       // conversion visible before ldmatrix

        const uint32_t a_base = a16;
        const uint32_t b_base = sb[kt % 3];

        // fragment double buffers (unchanged mainloop)
        uint32_t afrag[2][4][4];
        uint32_t bfrag[2][4][4];

        // prefetch h=0
#pragma unroll
        for (int mt = 0; mt < 4; mt++)
            ldmx4(afrag[0][mt],
                  a_base + ((a_lrow + mt * 16) * ROWB) * 2 + a_lcol);
#pragma unroll
        for (int nt2 = 0; nt2 < 4; nt2++)
            ldmx4(bfrag[0][nt2],
                  b_base + ((b_lrow + nt2 * 16) * ROWB) * 2 + b_lcol);

#pragma unroll
        for (int h = 0; h < HALVES; h++) {
            const int cur = h & 1;
            if (h + 1 < HALVES) {
                const int nxt = cur ^ 1;
                const int off = (h + 1) * 32;
#pragma unroll
                for (int mt = 0; mt < 4; mt++)
                    ldmx4(afrag[nxt][mt],
                          a_base + ((a_lrow + mt * 16) * ROWB) * 2 + off + a_lcol);
#pragma unroll
                for (int nt2 = 0; nt2 < 4; nt2++)
                    ldmx4(bfrag[nxt][nt2],
                          b_base + ((b_lrow + nt2 * 16) * ROWB) * 2 + off + b_lcol);
            }
#pragma unroll
            for (int mt = 0; mt < 4; mt++)
#pragma unroll
                for (int nt2 = 0; nt2 < 4; nt2++) {
                    hmma(acc[mt][nt2 * 2 + 0], afrag[cur][mt], &bfrag[cur][nt2][0]);
                    hmma(acc[mt][nt2 * 2 + 1], afrag[cur][mt], &bfrag[cur][nt2][2]);
                }
        }

        // issue tile kt+2: A -> staging[kt&1] (conversion reads of it completed
        // before this iteration's second barrier, which all threads passed);
        // B -> stage (kt+2)%3, consumed at iter kt-1 (all warps passed this
        // iteration's first barrier). One commit/iter keeps cp_wait<1> aligned.
        if (kt + 2 < KITERS) issue_tile(kt + 2);
        else cp_commit();       // keep group count uniform for cp_wait<1>
    }

    // epilogue
#pragma unroll
    for (int mt = 0; mt < 4; mt++) {
        const int row0 = bm + warp_m + mt * 16 + (lid >> 2);
#pragma unroll
        for (int nt = 0; nt < 8; nt++) {
            const int col = bn + warp_n + nt * 8 + 2 * (lid & 3);
            float2 v0 = {acc[mt][nt][0], acc[mt][nt][1]};
            float2 v1 = {acc[mt][nt][2], acc[mt][nt][3]};
            *reinterpret_cast<float2*>(&C[(size_t)row0 * OUT + col]) = v0;
            *reinterpret_cast<float2*>(&C[(size_t)(row0 + 8) * OUT + col]) = v1;
        }
    }
}

// ============================ launch ============================
extern "C" void kernel_launch(void* const* d_in, const int* in_sizes, int n_in,
                              void* d_out, int out_size)
{
    const float* x    = (const float*)d_in[0];   // [8192,1024]
    const float* coef = (const float*)d_in[1];   // [1024,1024,8]
    const float* w    = (const float*)d_in[2];   // [1024,1024]
    float* out        = (float*)d_out;           // [8192,1024]
    (void)in_sizes; (void)n_in; (void)out_size;

    static int attr_set = 0;
    if (!attr_set) {
        cudaFuncSetAttribute(gemm_hmma,
                             cudaFuncAttributeMaxDynamicSharedMemorySize, SMEM_BYTES);
        attr_set = 1;
    }

    weff_kernel<<<WB, 256>>>(coef, w);

    dim3 grid(OUT / BN, BATCH / BM);   // (8, 32) = 256 CTAs
    gemm_hmma<<<grid, 256, SMEM_BYTES>>>(x, out);
}

// round 15
// speedup vs baseline: 1.1414x; 1.1414x over previous
#include <cuda_runtime.h>
#include <cuda_fp16.h>
#include <cstdint>

// out[b,o] = x @ w_eff^T,  w_eff[o,i] = (sum_p coef[o,i,p]) * weights[o,i]
// Single fp16 GEMM on HMMA (m16n8k16, fp32 accum): C = fp16(x) @ fp16(w_eff)^T
// rel_err 2.93e-4 (calibrated), threshold 1e-3.
// FINAL = R11 config (best measured 74.2us):
//   GEMM: 256x128x64, 3-stage cp.async, fragment double-buffering — at the
//         sm_103a legacy mma.sync issue-rate floor (confirmed by R8/R9/R11).
//   prep: fused convert+w_eff kernel — at HBM traffic floor (confirmed R12).
//   Neighbors all measured worse: +occupancy (R9), +stages/early-issue (R10),
//   wider prep (R12), in-GEMM conversion fusion (R14).

#define BATCH 8192
#define IN    1024
#define OUT   1024
#define PDIM  8

__device__ __half g_ahi[BATCH * IN];
__device__ __half g_bhi[OUT * IN];   // [O,I] row-major == B^T [N,K]

// ============================ fused prep kernel ============================
// blocks [0, XB): convert x -> fp16, 8 floats/thread
// blocks [XB, XB+WB): build w_eff fp16, 2 outputs/thread
#define XB ((BATCH * IN / 8) / 256)   // 4096
#define WB ((OUT * IN / 2) / 256)     // 2048

__global__ __launch_bounds__(256) void prep_kernel(
    const float* __restrict__ x,
    const float* __restrict__ coef,
    const float* __restrict__ w)
{
    if (blockIdx.x < XB) {
        int idx = blockIdx.x * 256 + threadIdx.x;          // over BATCH*IN/8
        const float4* p = reinterpret_cast<const float4*>(x) + (size_t)idx * 2;
        float4 v0 = p[0];
        float4 v1 = p[1];
        union { __half h[8]; uint4 u; } o;
        o.h[0] = __float2half_rn(v0.x); o.h[1] = __float2half_rn(v0.y);
        o.h[2] = __float2half_rn(v0.z); o.h[3] = __float2half_rn(v0.w);
        o.h[4] = __float2half_rn(v1.x); o.h[5] = __float2half_rn(v1.y);
        o.h[6] = __float2half_rn(v1.z); o.h[7] = __float2half_rn(v1.w);
        reinterpret_cast<uint4*>(g_ahi)[idx] = o.u;
    } else {
        int i2 = (blockIdx.x - XB) * 256 + threadIdx.x;    // over O*I/2
        const float4* c4 = reinterpret_cast<const float4*>(coef) + (size_t)i2 * 4;
        float4 a0 = c4[0], a1 = c4[1], a2 = c4[2], a3 = c4[3];
        float2 wv = reinterpret_cast<const float2*>(w)[i2];
        float s0 = (((a0.x + a0.y) + (a0.z + a0.w)) + ((a1.x + a1.y) + (a1.z + a1.w))) * wv.x;
        float s1 = (((a2.x + a2.y) + (a2.z + a2.w)) + ((a3.x + a3.y) + (a3.z + a3.w))) * wv.y;
        union { __half h[2]; uint32_t u; } o;
        o.h[0] = __float2half_rn(s0);
        o.h[1] = __float2half_rn(s1);
        reinterpret_cast<uint32_t*>(g_bhi)[i2] = o.u;
    }
}

// ============================ GEMM (R8/R11 config — DO NOT PERTURB) ========
// Block 256x128x64, 256 threads (8 warps, 4x2), warp tile 64x64.
// 3-stage cp.async pipeline, 1 syncthreads per k-iter (16 iters).
// Fragment double-buffering: LDSM for k16-half h+1 issued before HMMAs of h.
// issue_tile at END of iteration (overlaps HMMA tail, not LDSM prefetch).
#define BM 256
#define BN 128
#define BK 64
#define KITERS 16          // 1024/64
#define STAGES 3
#define HALVES 4           // k16 halves per BK=64

#define ROWB 72            // halfs per smem row (144B stride, conflict-free)
#define A_STG (BM * ROWB)
#define B_STG (BN * ROWB)
#define STG   (A_STG + B_STG)
#define SMEM_BYTES (STAGES * STG * 2)   // 165,888

__device__ __forceinline__ uint32_t smem_u32(const void* p) {
    uint32_t a;
    asm("{ .reg .u64 t; cvta.to.shared.u64 t, %1; cvt.u32.u64 %0, t; }" : "=r"(a) : "l"(p));
    return a;
}
__device__ __forceinline__ void cp16(uint32_t dst, const void* src) {
    asm volatile("cp.async.cg.shared.global [%0], [%1], 16;" :: "r"(dst), "l"(src));
}
__device__ __forceinline__ void cp_commit() {
    asm volatile("cp.async.commit_group;");
}
template <int N>
__device__ __forceinline__ void cp_wait() {
    asm volatile("cp.async.wait_group %0;" :: "n"(N));
}
__device__ __forceinline__ void ldmx4(uint32_t* r, uint32_t addr) {
    asm volatile("ldmatrix.sync.aligned.m8n8.x4.shared.b16 {%0,%1,%2,%3}, [%4];"
                 : "=r"(r[0]), "=r"(r[1]), "=r"(r[2]), "=r"(r[3]) : "r"(addr));
}
__device__ __forceinline__ void hmma(float* c, const uint32_t* a, const uint32_t* b) {
    asm volatile(
        "mma.sync.aligned.m16n8k16.row.col.f32.f16.f16.f32 "
        "{%0,%1,%2,%3}, {%4,%5,%6,%7}, {%8,%9}, {%0,%1,%2,%3};"
        : "+f"(c[0]), "+f"(c[1]), "+f"(c[2]), "+f"(c[3])
        : "r"(a[0]), "r"(a[1]), "r"(a[2]), "r"(a[3]), "r"(b[0]), "r"(b[1]));
}

__global__ __launch_bounds__(256, 1) void gemm_hmma(float* __restrict__ C)
{
    extern __shared__ __half smem[];

    const int tid = threadIdx.x;
    const int wid = tid >> 5;
    const int lid = tid & 31;
    const int warp_m = (wid & 3) * 64;     // 4 warps along M
    const int warp_n = (wid >> 2) * 64;    // 2 warps along N

    const int bm = blockIdx.y * BM;
    const int bn = blockIdx.x * BN;

    // cp.async mapping: rows carry 128B data, 8 x 16B chunks per row.
    // A stage = 256 rows (8 chunks/thread), B stage = 128 rows (4 chunks/thread).
    const int ld_row = tid >> 3;           // 0..31
    const int ld_seg = (tid & 7) * 8;      // half offset in row: 0..56

    uint32_t stg_base[STAGES];
#pragma unroll
    for (int s = 0; s < STAGES; s++) stg_base[s] = smem_u32(smem + s * STG);

    float acc[4][8][4];
#pragma unroll
    for (int i = 0; i < 4; i++)
#pragma unroll
        for (int j = 0; j < 8; j++)
#pragma unroll
            for (int q = 0; q < 4; q++) acc[i][j][q] = 0.f;

    // ldmatrix lane addressing (byte offsets within tile)
    const int a_lrow = warp_m + (lid & 15);
    const int a_lcol = (lid >> 4) * 16;
    const int b_lrow = warp_n + ((lid >> 4) << 3) + (lid & 7);
    const int b_lcol = ((lid >> 3) & 1) * 16;

    auto issue_tile = [&](int kt, int stage) {
        const int ko = kt * BK;
        const uint32_t ab = stg_base[stage];
        const uint32_t bb = ab + A_STG * 2;
#pragma unroll
        for (int q = 0; q < 8; q++) {
            const int row = ld_row + q * 32;
            cp16(ab + (row * ROWB + ld_seg) * 2,
                 &g_ahi[(size_t)(bm + row) * IN + ko + ld_seg]);
        }
#pragma unroll
        for (int q = 0; q < 4; q++) {
            const int row = ld_row + q * 32;
            cp16(bb + (row * ROWB + ld_seg) * 2,
                 &g_bhi[(size_t)(bn + row) * IN + ko + ld_seg]);
        }
        cp_commit();
    };

    issue_tile(0, 0);
    issue_tile(1, 1);

    for (int kt = 0; kt < KITERS; kt++) {
        const int stage = kt % STAGES;
        cp_wait<1>();          // tile kt complete (kt+1 may be in flight)
        __syncthreads();

        const uint32_t a_base = stg_base[stage];
        const uint32_t b_base = a_base + A_STG * 2;

        // fragment double buffers
        uint32_t afrag[2][4][4];
        uint32_t bfrag[2][4][4];

        // prefetch h=0
#pragma unroll
        for (int mt = 0; mt < 4; mt++)
            ldmx4(afrag[0][mt],
                  a_base + ((a_lrow + mt * 16) * ROWB) * 2 + a_lcol);
#pragma unroll
        for (int nt2 = 0; nt2 < 4; nt2++)
            ldmx4(bfrag[0][nt2],
                  b_base + ((b_lrow + nt2 * 16) * ROWB) * 2 + b_lcol);

#pragma unroll
        for (int h = 0; h < HALVES; h++) {
            const int cur = h & 1;
            if (h + 1 < HALVES) {
                const int nxt = cur ^ 1;
                const int off = (h + 1) * 32;
#pragma unroll
                for (int mt = 0; mt < 4; mt++)
                    ldmx4(afrag[nxt][mt],
                          a_base + ((a_lrow + mt * 16) * ROWB) * 2 + off + a_lcol);
#pragma unroll
                for (int nt2 = 0; nt2 < 4; nt2++)
                    ldmx4(bfrag[nxt][nt2],
                          b_base + ((b_lrow + nt2 * 16) * ROWB) * 2 + off + b_lcol);
            }
#pragma unroll
            for (int mt = 0; mt < 4; mt++)
#pragma unroll
                for (int nt2 = 0; nt2 < 4; nt2++) {
                    hmma(acc[mt][nt2 * 2 + 0], afrag[cur][mt], &bfrag[cur][nt2][0]);
                    hmma(acc[mt][nt2 * 2 + 1], afrag[cur][mt], &bfrag[cur][nt2][2]);
                }
        }

        // issue tile kt+2 into the stage consumed at iter kt-1 (all warps
        // passed this iteration's barrier). Wraparound keeps cp.async group
        // counts uniform so cp_wait<1> stays aligned.
        issue_tile((kt + 2) % KITERS, (kt + 2) % STAGES);
    }

    // epilogue
#pragma unroll
    for (int mt = 0; mt < 4; mt++) {
        const int row0 = bm + warp_m + mt * 16 + (lid >> 2);
#pragma unroll
        for (int nt = 0; nt < 8; nt++) {
            const int col = bn + warp_n + nt * 8 + 2 * (lid & 3);
            float2 v0 = {acc[mt][nt][0], acc[mt][nt][1]};
            float2 v1 = {acc[mt][nt][2], acc[mt][nt][3]};
            *reinterpret_cast<float2*>(&C[(size_t)row0 * OUT + col]) = v0;
            *reinterpret_cast<float2*>(&C[(size_t)(row0 + 8) * OUT + col]) = v1;
        }
    }
}

// ============================ launch ============================
extern "C" void kernel_launch(void* const* d_in, const int* in_sizes, int n_in,
                              void* d_out, int out_size)
{
    const float* x    = (const float*)d_in[0];   // [8192,1024]
    const float* coef = (const float*)d_in[1];   // [1024,1024,8]
    const float* w    = (const float*)d_in[2];   // [1024,1024]
    float* out        = (float*)d_out;           // [8192,1024]
    (void)in_sizes; (void)n_in; (void)out_size;

    static int attr_set = 0;
    if (!attr_set) {
        cudaFuncSetAttribute(gemm_hmma,
                             cudaFuncAttributeMaxDynamicSharedMemorySize, SMEM_BYTES);
        attr_set = 1;
    }

    prep_kernel<<<XB + WB, 256>>>(x, coef, w);

    dim3 grid(OUT / BN, BATCH / BM);   // (8, 32) = 256 CTAs
    gemm_hmma<<<grid, 256, SMEM_BYTES>>>(out);
}